// round 12
// baseline (speedup 1.0000x reference)
#include <cuda_runtime.h>
#include <cuda_fp16.h>
#include <math.h>
#include <stdint.h>

// Problem constants: B=2, S=2048 -> T=4096 tokens, D=768, F=3072, E=8
#define T_TOK 4096
#define D_MODEL 768
#define F_FF 3072
#define N_EXP 8

#define BK 32
#define STAGES 4
#define NK1 (D_MODEL / BK)   // 24
#define NK2 (F_FF / BK)      // 96
#define MT1 32               // m-tiles/expert, BM=128 (gemm1)
#define MT2 64               // m-tiles/expert, BM=64  (gemm2)

// smem row stride: 40 halves = 80 bytes (conflict-free for LDSM: m*20 mod 32 spans all banks)
#define ROWB 80
#define A1_BYTES (128 * ROWB)
#define B_BYTES  (128 * ROWB)
#define STAGE1 (A1_BYTES + B_BYTES)      // 20480
#define SMEM1 (STAGES * STAGE1)          // 81920
#define A2_BYTES (64 * ROWB)
#define STAGE2 (A2_BYTES + B_BYTES)      // 15360
#define SMEM2 (STAGES * STAGE2)          // 61440

// -------- device scratch --------
__device__ __half g_h[T_TOK * F_FF];          // packed relu(x@wi), fp16
__device__ __half g_xh[T_TOK * D_MODEL];      // fp16 x
__device__ __half g_wit[N_EXP * F_FF * D_MODEL];  // wi transposed: [e][n=F][k=D]
__device__ __half g_wot[N_EXP * D_MODEL * F_FF];  // wo transposed: [e][n=D][k=F]
__device__ int   g_count[N_EXP];
__device__ int   g_base[N_EXP];
__device__ int   g_fill[N_EXP];
__device__ float g_rpsum[N_EXP];
__device__ int   g_routes[T_TOK];
__device__ int   g_perm[T_TOK];

// ---------------------------------------------------------------
__device__ __forceinline__ uint32_t smem_u32(const void* p) {
    uint32_t a;
    asm("{ .reg .u64 t; cvta.to.shared.u64 t, %1; cvt.u32.u64 %0, t; }"
        : "=r"(a) : "l"(p));
    return a;
}
__device__ __forceinline__ void mma_f16(
    float& c0, float& c1, float& c2, float& c3,
    uint32_t a0, uint32_t a1, uint32_t a2, uint32_t a3,
    uint32_t b0, uint32_t b1)
{
    asm volatile(
        "mma.sync.aligned.m16n8k16.row.col.f32.f16.f16.f32 "
        "{%0,%1,%2,%3}, {%4,%5,%6,%7}, {%8,%9}, {%0,%1,%2,%3};\n"
        : "+f"(c0), "+f"(c1), "+f"(c2), "+f"(c3)
        : "r"(a0), "r"(a1), "r"(a2), "r"(a3), "r"(b0), "r"(b1));
}
__device__ __forceinline__ void ldsm4(uint32_t& r0, uint32_t& r1,
                                      uint32_t& r2, uint32_t& r3, uint32_t addr)
{
    asm volatile("ldmatrix.sync.aligned.m8n8.x4.shared.b16 {%0,%1,%2,%3}, [%4];"
                 : "=r"(r0), "=r"(r1), "=r"(r2), "=r"(r3) : "r"(addr));
}
__device__ __forceinline__ void cp16(uint32_t dst, const void* src, uint32_t sz) {
    asm volatile("cp.async.cg.shared.global [%0], [%1], 16, %2;"
                 :: "r"(dst), "l"(src), "r"(sz) : "memory");
}
__device__ __forceinline__ void cp_commit() {
    asm volatile("cp.async.commit_group;" ::: "memory");
}
template<int N> __device__ __forceinline__ void cp_wait() {
    asm volatile("cp.async.wait_group %0;" :: "n"(N) : "memory");
}

// ---------------------------------------------------------------
__global__ void reset_kernel() {
    int i = threadIdx.x;
    if (i < N_EXP) { g_count[i] = 0; g_fill[i] = 0; g_rpsum[i] = 0.0f; }
}

// fp32 -> fp16 copy (float4 -> 4 halves)
__global__ __launch_bounds__(256) void cvt_kernel(
    const float* __restrict__ src, __half* __restrict__ dst, int n4)
{
    int i = blockIdx.x * blockDim.x + threadIdx.x;
    int stride = gridDim.x * blockDim.x;
    for (; i < n4; i += stride) {
        float4 v = ((const float4*)src)[i];
        __half2 lo = __floats2half2_rn(v.x, v.y);
        __half2 hi = __floats2half2_rn(v.z, v.w);
        uint2 o = make_uint2(*(uint32_t*)&lo, *(uint32_t*)&hi);
        ((uint2*)dst)[i] = o;
    }
}

// fp32 [e][K][N] -> fp16 [e][N][K]  (tiled transpose + convert)
__global__ __launch_bounds__(256) void cvtT_kernel(
    const float* __restrict__ src, __half* __restrict__ dst, int K, int N)
{
    __shared__ __half tile[32][33];
    int e = blockIdx.z;
    const float* s = src + (size_t)e * K * N;
    __half* d = dst + (size_t)e * N * K;
    int n0 = blockIdx.x * 32, k0 = blockIdx.y * 32;
    int tx = threadIdx.x & 31, ty = threadIdx.x >> 5;   // 32 x 8
#pragma unroll
    for (int j = 0; j < 4; j++)
        tile[ty + 8 * j][tx] = __float2half_rn(s[(size_t)(k0 + ty + 8 * j) * N + n0 + tx]);
    __syncthreads();
#pragma unroll
    for (int j = 0; j < 4; j++)
        d[(size_t)(n0 + ty + 8 * j) * K + k0 + tx] = tile[tx][ty + 8 * j];
}

// One warp per token, block-level reduction of counts/rpsum.
__global__ __launch_bounds__(256) void router_kernel(
    const float* __restrict__ x, const float* __restrict__ w,
    const float* __restrict__ b)
{
    __shared__ float sw[D_MODEL * N_EXP];
    __shared__ float s_rp[N_EXP];
    __shared__ int   s_cnt[N_EXP];
    if (threadIdx.x < N_EXP) { s_rp[threadIdx.x] = 0.0f; s_cnt[threadIdx.x] = 0; }
    for (int i = threadIdx.x; i < D_MODEL * N_EXP; i += blockDim.x) sw[i] = w[i];
    __syncthreads();

    int warp = threadIdx.x >> 5;
    int lane = threadIdx.x & 31;
    int t = blockIdx.x * (blockDim.x >> 5) + warp;

    if (t < T_TOK) {
        float acc[N_EXP];
#pragma unroll
        for (int e = 0; e < N_EXP; e++) acc[e] = 0.0f;
        const float* xr = x + (size_t)t * D_MODEL;
        for (int d = lane; d < D_MODEL; d += 32) {
            float xv = xr[d];
#pragma unroll
            for (int e = 0; e < N_EXP; e++) acc[e] += xv * sw[d * N_EXP + e];
        }
#pragma unroll
        for (int e = 0; e < N_EXP; e++) {
#pragma unroll
            for (int off = 16; off > 0; off >>= 1)
                acc[e] += __shfl_xor_sync(0xFFFFFFFFu, acc[e], off);
        }
        if (lane == 0) {
            float l[N_EXP];
            float mx = -3.4e38f; int am = 0;
#pragma unroll
            for (int e = 0; e < N_EXP; e++) {
                l[e] = acc[e] + b[e];
                if (l[e] > mx) { mx = l[e]; am = e; }
            }
            float s = 0.0f, p[N_EXP];
#pragma unroll
            for (int e = 0; e < N_EXP; e++) { p[e] = __expf(l[e] - mx); s += p[e]; }
            float inv = 1.0f / s;
#pragma unroll
            for (int e = 0; e < N_EXP; e++) atomicAdd(&s_rp[e], p[e] * inv);
            g_routes[t] = am;
            atomicAdd(&s_cnt[am], 1);
        }
    }
    __syncthreads();
    if (threadIdx.x < N_EXP) {
        atomicAdd(&g_rpsum[threadIdx.x], s_rp[threadIdx.x]);
        atomicAdd(&g_count[threadIdx.x], s_cnt[threadIdx.x]);
    }
}

__global__ void finalize_kernel(float* __restrict__ out, int out_size) {
    if (threadIdx.x == 0 && blockIdx.x == 0) {
        int run = 0;
        for (int e = 0; e < N_EXP; e++) { g_base[e] = run; run += g_count[e]; }
        if (out_size >= T_TOK * D_MODEL + 2 * N_EXP + 1) {
            float* tail = out + (size_t)T_TOK * D_MODEL;
            for (int e = 0; e < N_EXP; e++) tail[e] = (float)g_count[e];
            for (int e = 0; e < N_EXP; e++) tail[N_EXP + e] = g_rpsum[e];
            tail[2 * N_EXP] = 0.0f;
        }
    }
}

__global__ void perm_kernel() {
    int t = blockIdx.x * blockDim.x + threadIdx.x;
    if (t >= T_TOK) return;
    int e = g_routes[t];
    int p = g_base[e] + atomicAdd(&g_fill[e], 1);
    g_perm[p] = t;
}

// ---------------------------------------------------------------
// GEMM1: h[m,n] = relu( sum_k xh[perm(m),k] * wit[e][n][k] )  (fp16, fp32 acc)
// BM=128, BN=128, BK=32, 4-stage cp.async, ldmatrix fragments.
// ---------------------------------------------------------------
__global__ __launch_bounds__(256, 2) void gemm1_kernel(
    const __half* __restrict__ wi_t)
{
    int e  = blockIdx.y >> 5;
    int mt = blockIdx.y & 31;
    int cnt = g_count[e];
    int m0 = mt * 128;
    if (m0 >= cnt) return;
    int base = g_base[e];
    int n0 = blockIdx.x * 128;
    const __half* Bg = wi_t + (size_t)e * F_FF * D_MODEL;   // [n][k], k-stride D

    extern __shared__ char dsm[];
    uint32_t sbase = smem_u32(dsm);

    int tid  = threadIdx.x;
    int lane = tid & 31, warp = tid >> 5;
    int wm0 = (warp & 1) * 64, wn0 = (warp >> 1) * 32;
    int grp = lane >> 2, tig = lane & 3;

    // ldmatrix per-lane address components
    int mlane = lane & 15;             // row within 16-row A fragment
    int klo   = (lane >> 4) * 8;       // A: k offset halves (0/8); B: n offset (0/8)
    int kofB  = ((lane >> 3) & 1) * 8; // B: k offset halves (0/8)

    // cp.async mapping: row = tid>>2 (+64), chk = tid&3
    int arow0 = tid >> 2;
    int achk = tid & 3;
    const __half* apg[2]; uint32_t asz[2];
#pragma unroll
    for (int i = 0; i < 2; i++) {
        int r = m0 + arow0 + i * 64;
        if (r < cnt) { apg[i] = g_xh + (size_t)g_perm[base + r] * D_MODEL; asz[i] = 16; }
        else         { apg[i] = g_xh; asz[i] = 0; }
    }

    float acc[4][4][4];
#pragma unroll
    for (int mi = 0; mi < 4; mi++)
#pragma unroll
        for (int ni = 0; ni < 4; ni++)
#pragma unroll
            for (int q = 0; q < 4; q++) acc[mi][ni][q] = 0.0f;

#pragma unroll
    for (int s = 0; s < STAGES - 1; s++) {
        int kt = s * BK;
        uint32_t Ab = sbase + s * STAGE1;
        uint32_t Bb = Ab + A1_BYTES;
#pragma unroll
        for (int i = 0; i < 2; i++) {
            int row = arow0 + i * 64;
            cp16(Ab + (uint32_t)row * ROWB + (uint32_t)achk * 16u,
                 apg[i] + kt + achk * 8, asz[i]);
            cp16(Bb + (uint32_t)row * ROWB + (uint32_t)achk * 16u,
                 Bg + (size_t)(n0 + row) * D_MODEL + kt + achk * 8, 16);
        }
        cp_commit();
    }

    for (int it = 0; it < NK1; ++it) {
        cp_wait<STAGES - 2>();
        __syncthreads();
        {
            int pt = it + STAGES - 1;
            if (pt < NK1) {
                int s = pt % STAGES;
                int kt = pt * BK;
                uint32_t Ab = sbase + s * STAGE1;
                uint32_t Bb = Ab + A1_BYTES;
#pragma unroll
                for (int i = 0; i < 2; i++) {
                    int row = arow0 + i * 64;
                    cp16(Ab + (uint32_t)row * ROWB + (uint32_t)achk * 16u,
                         apg[i] + kt + achk * 8, asz[i]);
                    cp16(Bb + (uint32_t)row * ROWB + (uint32_t)achk * 16u,
                         Bg + (size_t)(n0 + row) * D_MODEL + kt + achk * 8, 16);
                }
            }
            cp_commit();
        }

        uint32_t As = sbase + (it % STAGES) * STAGE1;
        uint32_t Bs = As + A1_BYTES;
        uint32_t aA0 = As + (uint32_t)(wm0 + mlane) * ROWB + (uint32_t)klo * 2u;
        uint32_t aB0 = Bs + (uint32_t)(wn0 + (lane & 7) + klo) * ROWB + (uint32_t)kofB * 2u;
#pragma unroll
        for (int kk = 0; kk < 2; kk++) {
            uint32_t kb = (uint32_t)kk * 32u;   // kk*16 halves
            uint32_t a[4][4], b[4][2];
#pragma unroll
            for (int mi = 0; mi < 4; mi++)
                ldsm4(a[mi][0], a[mi][1], a[mi][2], a[mi][3],
                      aA0 + (uint32_t)mi * (16u * ROWB) + kb);
#pragma unroll
            for (int p = 0; p < 2; p++)
                ldsm4(b[2 * p][0], b[2 * p][1], b[2 * p + 1][0], b[2 * p + 1][1],
                      aB0 + (uint32_t)p * (16u * ROWB) + kb);
#pragma unroll
            for (int mi = 0; mi < 4; mi++)
#pragma unroll
                for (int ni = 0; ni < 4; ni++)
                    mma_f16(acc[mi][ni][0], acc[mi][ni][1], acc[mi][ni][2], acc[mi][ni][3],
                            a[mi][0], a[mi][1], a[mi][2], a[mi][3],
                            b[ni][0], b[ni][1]);
        }
        __syncthreads();
    }

    // epilogue: relu -> fp16 packed g_h
#pragma unroll
    for (int mi = 0; mi < 4; mi++) {
        int r0 = m0 + wm0 + mi * 16 + grp;
        int r1 = r0 + 8;
#pragma unroll
        for (int ni = 0; ni < 4; ni++) {
            int c = n0 + wn0 + ni * 8 + 2 * tig;
            if (r0 < cnt) {
                __half2 v = __floats2half2_rn(fmaxf(acc[mi][ni][0], 0.f),
                                              fmaxf(acc[mi][ni][1], 0.f));
                *(__half2*)&g_h[(size_t)(base + r0) * F_FF + c] = v;
            }
            if (r1 < cnt) {
                __half2 v = __floats2half2_rn(fmaxf(acc[mi][ni][2], 0.f),
                                              fmaxf(acc[mi][ni][3], 0.f));
                *(__half2*)&g_h[(size_t)(base + r1) * F_FF + c] = v;
            }
        }
    }
}

// ---------------------------------------------------------------
// GEMM2: out[perm(m),n] = sum_k h[m,k] * wot[e][n][k]
// BM=64, BN=128, BK=32, ldmatrix fragments.
// ---------------------------------------------------------------
__global__ __launch_bounds__(256, 2) void gemm2_kernel(
    const __half* __restrict__ wo_t, float* __restrict__ out)
{
    int e  = blockIdx.y >> 6;
    int mt = blockIdx.y & 63;
    int cnt = g_count[e];
    int m0 = mt * 64;
    if (m0 >= cnt) return;
    int base = g_base[e];
    int n0 = blockIdx.x * 128;
    const __half* Bg = wo_t + (size_t)e * D_MODEL * F_FF;   // [n][k], k-stride F

    extern __shared__ char dsm[];
    uint32_t sbase = smem_u32(dsm);

    int tid  = threadIdx.x;
    int lane = tid & 31, warp = tid >> 5;
    int wm0 = (warp & 1) * 32, wn0 = (warp >> 1) * 32;
    int grp = lane >> 2, tig = lane & 3;

    int mlane = lane & 15;
    int klo   = (lane >> 4) * 8;
    int kofB  = ((lane >> 3) & 1) * 8;

    int arow = tid >> 2;
    int achk = tid & 3;
    uint32_t asz = (m0 + arow < cnt) ? 16u : 0u;
    const __half* apg = g_h + (size_t)(base + ((m0 + arow < cnt) ? (m0 + arow) : 0)) * F_FF;

    float acc[2][4][4];
#pragma unroll
    for (int mi = 0; mi < 2; mi++)
#pragma unroll
        for (int ni = 0; ni < 4; ni++)
#pragma unroll
            for (int q = 0; q < 4; q++) acc[mi][ni][q] = 0.0f;

#pragma unroll
    for (int s = 0; s < STAGES - 1; s++) {
        int kt = s * BK;
        uint32_t Ab = sbase + s * STAGE2;
        uint32_t Bb = Ab + A2_BYTES;
        cp16(Ab + (uint32_t)arow * ROWB + (uint32_t)achk * 16u, apg + kt + achk * 8, asz);
#pragma unroll
        for (int i = 0; i < 2; i++) {
            int row = arow + i * 64;
            cp16(Bb + (uint32_t)row * ROWB + (uint32_t)achk * 16u,
                 Bg + (size_t)(n0 + row) * F_FF + kt + achk * 8, 16);
        }
        cp_commit();
    }

    for (int it = 0; it < NK2; ++it) {
        cp_wait<STAGES - 2>();
        __syncthreads();
        {
            int pt = it + STAGES - 1;
            if (pt < NK2) {
                int s = pt % STAGES;
                int kt = pt * BK;
                uint32_t Ab = sbase + s * STAGE2;
                uint32_t Bb = Ab + A2_BYTES;
                cp16(Ab + (uint32_t)arow * ROWB + (uint32_t)achk * 16u, apg + kt + achk * 8, asz);
#pragma unroll
                for (int i = 0; i < 2; i++) {
                    int row = arow + i * 64;
                    cp16(Bb + (uint32_t)row * ROWB + (uint32_t)achk * 16u,
                         Bg + (size_t)(n0 + row) * F_FF + kt + achk * 8, 16);
                }
            }
            cp_commit();
        }

        uint32_t As = sbase + (it % STAGES) * STAGE2;
        uint32_t Bs = As + A2_BYTES;
        uint32_t aA0 = As + (uint32_t)(wm0 + mlane) * ROWB + (uint32_t)klo * 2u;
        uint32_t aB0 = Bs + (uint32_t)(wn0 + (lane & 7) + klo) * ROWB + (uint32_t)kofB * 2u;
#pragma unroll
        for (int kk = 0; kk < 2; kk++) {
            uint32_t kb = (uint32_t)kk * 32u;
            uint32_t a[2][4], b[4][2];
#pragma unroll
            for (int mi = 0; mi < 2; mi++)
                ldsm4(a[mi][0], a[mi][1], a[mi][2], a[mi][3],
                      aA0 + (uint32_t)mi * (16u * ROWB) + kb);
#pragma unroll
            for (int p = 0; p < 2; p++)
                ldsm4(b[2 * p][0], b[2 * p][1], b[2 * p + 1][0], b[2 * p + 1][1],
                      aB0 + (uint32_t)p * (16u * ROWB) + kb);
#pragma unroll
            for (int mi = 0; mi < 2; mi++)
#pragma unroll
                for (int ni = 0; ni < 4; ni++)
                    mma_f16(acc[mi][ni][0], acc[mi][ni][1], acc[mi][ni][2], acc[mi][ni][3],
                            a[mi][0], a[mi][1], a[mi][2], a[mi][3],
                            b[ni][0], b[ni][1]);
        }
        __syncthreads();
    }

    // epilogue: scatter fp32 to out[perm]
#pragma unroll
    for (int mi = 0; mi < 2; mi++) {
        int r0 = m0 + wm0 + mi * 16 + grp;
        int r1 = r0 + 8;
        int t0 = (r0 < cnt) ? g_perm[base + r0] : -1;
        int t1 = (r1 < cnt) ? g_perm[base + r1] : -1;
#pragma unroll
        for (int ni = 0; ni < 4; ni++) {
            int c = n0 + wn0 + ni * 8 + 2 * tig;
            if (t0 >= 0) {
                float2 v = make_float2(acc[mi][ni][0], acc[mi][ni][1]);
                *(float2*)&out[(size_t)t0 * D_MODEL + c] = v;
            }
            if (t1 >= 0) {
                float2 v = make_float2(acc[mi][ni][2], acc[mi][ni][3]);
                *(float2*)&out[(size_t)t1 * D_MODEL + c] = v;
            }
        }
    }
}

// ---------------------------------------------------------------
extern "C" void kernel_launch(void* const* d_in, const int* in_sizes, int n_in,
                              void* d_out, int out_size) {
    const float* x  = (const float*)d_in[0];
    const float* ws = (const float*)d_in[1];
    const float* bs = (const float*)d_in[2];
    const float* wi = (const float*)d_in[3];
    const float* wo = (const float*)d_in[4];
    float* out = (float*)d_out;

    static __half* wit_p = nullptr;
    static __half* wot_p = nullptr;
    static __half* xh_p = nullptr;
    if (!wit_p) {
        cudaGetSymbolAddress((void**)&wit_p, g_wit);
        cudaGetSymbolAddress((void**)&wot_p, g_wot);
        cudaGetSymbolAddress((void**)&xh_p, g_xh);
        cudaFuncSetAttribute(gemm1_kernel, cudaFuncAttributeMaxDynamicSharedMemorySize, SMEM1);
        cudaFuncSetAttribute(gemm2_kernel, cudaFuncAttributeMaxDynamicSharedMemorySize, SMEM2);
    }

    reset_kernel<<<1, 32>>>();
    cvt_kernel<<<512, 256>>>(x, xh_p, T_TOK * D_MODEL / 4);
    // wi: [K=768][N=3072] -> [N][K];  wo: [K=3072][N=768] -> [N][K]
    cvtT_kernel<<<dim3(F_FF / 32, D_MODEL / 32, N_EXP), 256>>>(wi, wit_p, D_MODEL, F_FF);
    cvtT_kernel<<<dim3(D_MODEL / 32, F_FF / 32, N_EXP), 256>>>(wo, wot_p, F_FF, D_MODEL);
    router_kernel<<<T_TOK / 8, 256>>>(x, ws, bs);
    finalize_kernel<<<1, 1>>>(out, out_size);
    perm_kernel<<<T_TOK / 256, 256>>>();
    gemm1_kernel<<<dim3(F_FF / 128, N_EXP * MT1), 256, SMEM1>>>(wit_p);
    gemm2_kernel<<<dim3(D_MODEL / 128, N_EXP * MT2), 256, SMEM2>>>(wot_p, out);
}

// round 13
// speedup vs baseline: 1.1116x; 1.1116x over previous
#include <cuda_runtime.h>
#include <cuda_fp16.h>
#include <math.h>
#include <stdint.h>

// Problem constants: B=2, S=2048 -> T=4096 tokens, D=768, F=3072, E=8
#define T_TOK 4096
#define D_MODEL 768
#define F_FF 3072
#define N_EXP 8

#define BK 32
#define STAGES 4
#define NK1 (D_MODEL / BK)   // 24
#define NK2 (F_FF / BK)      // 96
#define MT1 32               // m-tiles/expert, BM=128 (gemm1)
#define MT2 64               // m-tiles/expert, BM=64  (gemm2)

// smem row stride: 40 halves = 80 bytes (conflict-free for LDSM)
#define ROWB 80
#define A1_BYTES (128 * ROWB)
#define B_BYTES  (128 * ROWB)
#define STAGE1 (A1_BYTES + B_BYTES)      // 20480
#define SMEM1 (STAGES * STAGE1)          // 81920
#define A2_BYTES (64 * ROWB)
#define STAGE2 (A2_BYTES + B_BYTES)      // 15360
#define SMEM2 (STAGES * STAGE2)          // 61440

// -------- device scratch --------
__device__ __half g_h[T_TOK * F_FF];          // packed relu(x@wi), fp16
__device__ __half g_xh[T_TOK * D_MODEL];      // fp16 x
__device__ __half g_wit[N_EXP * F_FF * D_MODEL];  // wi transposed: [e][n=F][k=D]
__device__ __half g_wot[N_EXP * D_MODEL * F_FF];  // wo transposed: [e][n=D][k=F]
__device__ int   g_count[N_EXP];
__device__ int   g_base[N_EXP];
__device__ int   g_fill[N_EXP];
__device__ float g_rpsum[N_EXP];
__device__ int   g_routes[T_TOK];
__device__ int   g_perm[T_TOK];

// ---------------------------------------------------------------
__device__ __forceinline__ uint32_t smem_u32(const void* p) {
    uint32_t a;
    asm("{ .reg .u64 t; cvta.to.shared.u64 t, %1; cvt.u32.u64 %0, t; }"
        : "=r"(a) : "l"(p));
    return a;
}
__device__ __forceinline__ void mma_f16(
    float& c0, float& c1, float& c2, float& c3,
    uint32_t a0, uint32_t a1, uint32_t a2, uint32_t a3,
    uint32_t b0, uint32_t b1)
{
    asm volatile(
        "mma.sync.aligned.m16n8k16.row.col.f32.f16.f16.f32 "
        "{%0,%1,%2,%3}, {%4,%5,%6,%7}, {%8,%9}, {%0,%1,%2,%3};\n"
        : "+f"(c0), "+f"(c1), "+f"(c2), "+f"(c3)
        : "r"(a0), "r"(a1), "r"(a2), "r"(a3), "r"(b0), "r"(b1));
}
__device__ __forceinline__ void ldsm4(uint32_t& r0, uint32_t& r1,
                                      uint32_t& r2, uint32_t& r3, uint32_t addr)
{
    asm volatile("ldmatrix.sync.aligned.m8n8.x4.shared.b16 {%0,%1,%2,%3}, [%4];"
                 : "=r"(r0), "=r"(r1), "=r"(r2), "=r"(r3) : "r"(addr));
}
__device__ __forceinline__ void cp16(uint32_t dst, const void* src, uint32_t sz) {
    asm volatile("cp.async.cg.shared.global [%0], [%1], 16, %2;"
                 :: "r"(dst), "l"(src), "r"(sz) : "memory");
}
__device__ __forceinline__ void cp_commit() {
    asm volatile("cp.async.commit_group;" ::: "memory");
}
template<int N> __device__ __forceinline__ void cp_wait() {
    asm volatile("cp.async.wait_group %0;" :: "n"(N) : "memory");
}

// ---------------------------------------------------------------
__global__ void reset_kernel() {
    int i = threadIdx.x;
    if (i < N_EXP) { g_count[i] = 0; g_fill[i] = 0; g_rpsum[i] = 0.0f; }
}

// fp32 -> fp16 copy (float4 -> 4 halves)
__global__ __launch_bounds__(256) void cvt_kernel(
    const float* __restrict__ src, __half* __restrict__ dst, int n4)
{
    int i = blockIdx.x * blockDim.x + threadIdx.x;
    int stride = gridDim.x * blockDim.x;
    for (; i < n4; i += stride) {
        float4 v = ((const float4*)src)[i];
        __half2 lo = __floats2half2_rn(v.x, v.y);
        __half2 hi = __floats2half2_rn(v.z, v.w);
        uint2 o = make_uint2(*(uint32_t*)&lo, *(uint32_t*)&hi);
        ((uint2*)dst)[i] = o;
    }
}

// fp32 [e][K][N] -> fp16 [e][N][K]  (64x64 tiles, vectorized both sides)
#define TP 66
__global__ __launch_bounds__(256) void cvtT_kernel(
    const float* __restrict__ src, __half* __restrict__ dst, int K, int N)
{
    __shared__ __half tile[64][TP];
    int e = blockIdx.z;
    const float* s = src + (size_t)e * K * N;
    __half* d = dst + (size_t)e * N * K;
    int n0 = blockIdx.x * 64, k0 = blockIdx.y * 64;

    int tx = threadIdx.x & 15, ty = threadIdx.x >> 4;   // 16 x 16
#pragma unroll
    for (int j = 0; j < 4; j++) {
        int k = ty + 16 * j;
        float4 v = *(const float4*)(s + (size_t)(k0 + k) * N + n0 + tx * 4);
        __half2 h01 = __floats2half2_rn(v.x, v.y);
        __half2 h23 = __floats2half2_rn(v.z, v.w);
        *(__half2*)&tile[k][tx * 4]     = h01;
        *(__half2*)&tile[k][tx * 4 + 2] = h23;
    }
    __syncthreads();

    int nr = threadIdx.x >> 2;          // output n-row 0..63
    int kc = (threadIdx.x & 3) * 16;    // k chunk
    __half vals[16];
#pragma unroll
    for (int i = 0; i < 16; i++) vals[i] = tile[kc + i][nr];
    __half* drow = d + (size_t)(n0 + nr) * K + k0 + kc;
    *(uint4*)(drow)     = *(uint4*)&vals[0];
    *(uint4*)(drow + 8) = *(uint4*)&vals[8];
}

// One warp per token, block-level reduction of counts/rpsum.
__global__ __launch_bounds__(256) void router_kernel(
    const float* __restrict__ x, const float* __restrict__ w,
    const float* __restrict__ b)
{
    __shared__ float sw[D_MODEL * N_EXP];
    __shared__ float s_rp[N_EXP];
    __shared__ int   s_cnt[N_EXP];
    if (threadIdx.x < N_EXP) { s_rp[threadIdx.x] = 0.0f; s_cnt[threadIdx.x] = 0; }
    for (int i = threadIdx.x; i < D_MODEL * N_EXP; i += blockDim.x) sw[i] = w[i];
    __syncthreads();

    int warp = threadIdx.x >> 5;
    int lane = threadIdx.x & 31;
    int t = blockIdx.x * (blockDim.x >> 5) + warp;

    if (t < T_TOK) {
        float acc[N_EXP];
#pragma unroll
        for (int e = 0; e < N_EXP; e++) acc[e] = 0.0f;
        const float* xr = x + (size_t)t * D_MODEL;
        for (int d = lane; d < D_MODEL; d += 32) {
            float xv = xr[d];
#pragma unroll
            for (int e = 0; e < N_EXP; e++) acc[e] += xv * sw[d * N_EXP + e];
        }
#pragma unroll
        for (int e = 0; e < N_EXP; e++) {
#pragma unroll
            for (int off = 16; off > 0; off >>= 1)
                acc[e] += __shfl_xor_sync(0xFFFFFFFFu, acc[e], off);
        }
        if (lane == 0) {
            float l[N_EXP];
            float mx = -3.4e38f; int am = 0;
#pragma unroll
            for (int e = 0; e < N_EXP; e++) {
                l[e] = acc[e] + b[e];
                if (l[e] > mx) { mx = l[e]; am = e; }
            }
            float s = 0.0f, p[N_EXP];
#pragma unroll
            for (int e = 0; e < N_EXP; e++) { p[e] = __expf(l[e] - mx); s += p[e]; }
            float inv = 1.0f / s;
#pragma unroll
            for (int e = 0; e < N_EXP; e++) atomicAdd(&s_rp[e], p[e] * inv);
            g_routes[t] = am;
            atomicAdd(&s_cnt[am], 1);
        }
    }
    __syncthreads();
    if (threadIdx.x < N_EXP) {
        atomicAdd(&g_rpsum[threadIdx.x], s_rp[threadIdx.x]);
        atomicAdd(&g_count[threadIdx.x], s_cnt[threadIdx.x]);
    }
}

__global__ void finalize_kernel(float* __restrict__ out, int out_size) {
    if (threadIdx.x == 0 && blockIdx.x == 0) {
        int run = 0;
        for (int e = 0; e < N_EXP; e++) { g_base[e] = run; run += g_count[e]; }
        if (out_size >= T_TOK * D_MODEL + 2 * N_EXP + 1) {
            float* tail = out + (size_t)T_TOK * D_MODEL;
            for (int e = 0; e < N_EXP; e++) tail[e] = (float)g_count[e];
            for (int e = 0; e < N_EXP; e++) tail[N_EXP + e] = g_rpsum[e];
            tail[2 * N_EXP] = 0.0f;
        }
    }
}

__global__ void perm_kernel() {
    int t = blockIdx.x * blockDim.x + threadIdx.x;
    if (t >= T_TOK) return;
    int e = g_routes[t];
    int p = g_base[e] + atomicAdd(&g_fill[e], 1);
    g_perm[p] = t;
}

// ---------------------------------------------------------------
// GEMM1: h[m,n] = relu( sum_k xh[perm(m),k] * wit[e][n][k] )  (fp16, fp32 acc)
// BM=128, BN=128, BK=32, 4-stage cp.async, ldmatrix fragments.
// ---------------------------------------------------------------
__global__ __launch_bounds__(256, 2) void gemm1_kernel(
    const __half* __restrict__ wi_t)
{
    int e  = blockIdx.y >> 5;
    int mt = blockIdx.y & 31;
    int cnt = g_count[e];
    int m0 = mt * 128;
    if (m0 >= cnt) return;
    int base = g_base[e];
    int n0 = blockIdx.x * 128;
    const __half* Bg = wi_t + (size_t)e * F_FF * D_MODEL;   // [n][k], k-stride D

    extern __shared__ char dsm[];
    uint32_t sbase = smem_u32(dsm);

    int tid  = threadIdx.x;
    int lane = tid & 31, warp = tid >> 5;
    int wm0 = (warp & 1) * 64, wn0 = (warp >> 1) * 32;
    int grp = lane >> 2, tig = lane & 3;

    int mlane = lane & 15;
    int klo   = (lane >> 4) * 8;
    int kofB  = ((lane >> 3) & 1) * 8;

    int arow0 = tid >> 2;
    int achk = tid & 3;
    const __half* apg[2]; uint32_t asz[2];
#pragma unroll
    for (int i = 0; i < 2; i++) {
        int r = m0 + arow0 + i * 64;
        if (r < cnt) { apg[i] = g_xh + (size_t)g_perm[base + r] * D_MODEL; asz[i] = 16; }
        else         { apg[i] = g_xh; asz[i] = 0; }
    }

    float acc[4][4][4];
#pragma unroll
    for (int mi = 0; mi < 4; mi++)
#pragma unroll
        for (int ni = 0; ni < 4; ni++)
#pragma unroll
            for (int q = 0; q < 4; q++) acc[mi][ni][q] = 0.0f;

#pragma unroll
    for (int s = 0; s < STAGES - 1; s++) {
        int kt = s * BK;
        uint32_t Ab = sbase + s * STAGE1;
        uint32_t Bb = Ab + A1_BYTES;
#pragma unroll
        for (int i = 0; i < 2; i++) {
            int row = arow0 + i * 64;
            cp16(Ab + (uint32_t)row * ROWB + (uint32_t)achk * 16u,
                 apg[i] + kt + achk * 8, asz[i]);
            cp16(Bb + (uint32_t)row * ROWB + (uint32_t)achk * 16u,
                 Bg + (size_t)(n0 + row) * D_MODEL + kt + achk * 8, 16);
        }
        cp_commit();
    }

    for (int it = 0; it < NK1; ++it) {
        cp_wait<STAGES - 2>();
        __syncthreads();
        {
            int pt = it + STAGES - 1;
            if (pt < NK1) {
                int s = pt % STAGES;
                int kt = pt * BK;
                uint32_t Ab = sbase + s * STAGE1;
                uint32_t Bb = Ab + A1_BYTES;
#pragma unroll
                for (int i = 0; i < 2; i++) {
                    int row = arow0 + i * 64;
                    cp16(Ab + (uint32_t)row * ROWB + (uint32_t)achk * 16u,
                         apg[i] + kt + achk * 8, asz[i]);
                    cp16(Bb + (uint32_t)row * ROWB + (uint32_t)achk * 16u,
                         Bg + (size_t)(n0 + row) * D_MODEL + kt + achk * 8, 16);
                }
            }
            cp_commit();
        }

        uint32_t As = sbase + (it % STAGES) * STAGE1;
        uint32_t Bs = As + A1_BYTES;
        uint32_t aA0 = As + (uint32_t)(wm0 + mlane) * ROWB + (uint32_t)klo * 2u;
        uint32_t aB0 = Bs + (uint32_t)(wn0 + (lane & 7) + klo) * ROWB + (uint32_t)kofB * 2u;
#pragma unroll
        for (int kk = 0; kk < 2; kk++) {
            uint32_t kb = (uint32_t)kk * 32u;
            uint32_t a[4][4], b[4][2];
#pragma unroll
            for (int mi = 0; mi < 4; mi++)
                ldsm4(a[mi][0], a[mi][1], a[mi][2], a[mi][3],
                      aA0 + (uint32_t)mi * (16u * ROWB) + kb);
#pragma unroll
            for (int p = 0; p < 2; p++)
                ldsm4(b[2 * p][0], b[2 * p][1], b[2 * p + 1][0], b[2 * p + 1][1],
                      aB0 + (uint32_t)p * (16u * ROWB) + kb);
#pragma unroll
            for (int mi = 0; mi < 4; mi++)
#pragma unroll
                for (int ni = 0; ni < 4; ni++)
                    mma_f16(acc[mi][ni][0], acc[mi][ni][1], acc[mi][ni][2], acc[mi][ni][3],
                            a[mi][0], a[mi][1], a[mi][2], a[mi][3],
                            b[ni][0], b[ni][1]);
        }
        __syncthreads();
    }

    // epilogue: relu -> fp16 packed g_h
#pragma unroll
    for (int mi = 0; mi < 4; mi++) {
        int r0 = m0 + wm0 + mi * 16 + grp;
        int r1 = r0 + 8;
#pragma unroll
        for (int ni = 0; ni < 4; ni++) {
            int c = n0 + wn0 + ni * 8 + 2 * tig;
            if (r0 < cnt) {
                __half2 v = __floats2half2_rn(fmaxf(acc[mi][ni][0], 0.f),
                                              fmaxf(acc[mi][ni][1], 0.f));
                *(__half2*)&g_h[(size_t)(base + r0) * F_FF + c] = v;
            }
            if (r1 < cnt) {
                __half2 v = __floats2half2_rn(fmaxf(acc[mi][ni][2], 0.f),
                                              fmaxf(acc[mi][ni][3], 0.f));
                *(__half2*)&g_h[(size_t)(base + r1) * F_FF + c] = v;
            }
        }
    }
}

// ---------------------------------------------------------------
// GEMM2: out[perm(m),n] = sum_k h[m,k] * wot[e][n][k]
// BM=64, BN=128, BK=32, ldmatrix fragments.
// ---------------------------------------------------------------
__global__ __launch_bounds__(256, 2) void gemm2_kernel(
    const __half* __restrict__ wo_t, float* __restrict__ out)
{
    int e  = blockIdx.y >> 6;
    int mt = blockIdx.y & 63;
    int cnt = g_count[e];
    int m0 = mt * 64;
    if (m0 >= cnt) return;
    int base = g_base[e];
    int n0 = blockIdx.x * 128;
    const __half* Bg = wo_t + (size_t)e * D_MODEL * F_FF;   // [n][k], k-stride F

    extern __shared__ char dsm[];
    uint32_t sbase = smem_u32(dsm);

    int tid  = threadIdx.x;
    int lane = tid & 31, warp = tid >> 5;
    int wm0 = (warp & 1) * 32, wn0 = (warp >> 1) * 32;
    int grp = lane >> 2, tig = lane & 3;

    int mlane = lane & 15;
    int klo   = (lane >> 4) * 8;
    int kofB  = ((lane >> 3) & 1) * 8;

    int arow = tid >> 2;
    int achk = tid & 3;
    uint32_t asz = (m0 + arow < cnt) ? 16u : 0u;
    const __half* apg = g_h + (size_t)(base + ((m0 + arow < cnt) ? (m0 + arow) : 0)) * F_FF;

    float acc[2][4][4];
#pragma unroll
    for (int mi = 0; mi < 2; mi++)
#pragma unroll
        for (int ni = 0; ni < 4; ni++)
#pragma unroll
            for (int q = 0; q < 4; q++) acc[mi][ni][q] = 0.0f;

#pragma unroll
    for (int s = 0; s < STAGES - 1; s++) {
        int kt = s * BK;
        uint32_t Ab = sbase + s * STAGE2;
        uint32_t Bb = Ab + A2_BYTES;
        cp16(Ab + (uint32_t)arow * ROWB + (uint32_t)achk * 16u, apg + kt + achk * 8, asz);
#pragma unroll
        for (int i = 0; i < 2; i++) {
            int row = arow + i * 64;
            cp16(Bb + (uint32_t)row * ROWB + (uint32_t)achk * 16u,
                 Bg + (size_t)(n0 + row) * F_FF + kt + achk * 8, 16);
        }
        cp_commit();
    }

    for (int it = 0; it < NK2; ++it) {
        cp_wait<STAGES - 2>();
        __syncthreads();
        {
            int pt = it + STAGES - 1;
            if (pt < NK2) {
                int s = pt % STAGES;
                int kt = pt * BK;
                uint32_t Ab = sbase + s * STAGE2;
                uint32_t Bb = Ab + A2_BYTES;
                cp16(Ab + (uint32_t)arow * ROWB + (uint32_t)achk * 16u, apg + kt + achk * 8, asz);
#pragma unroll
                for (int i = 0; i < 2; i++) {
                    int row = arow + i * 64;
                    cp16(Bb + (uint32_t)row * ROWB + (uint32_t)achk * 16u,
                         Bg + (size_t)(n0 + row) * F_FF + kt + achk * 8, 16);
                }
            }
            cp_commit();
        }

        uint32_t As = sbase + (it % STAGES) * STAGE2;
        uint32_t Bs = As + A2_BYTES;
        uint32_t aA0 = As + (uint32_t)(wm0 + mlane) * ROWB + (uint32_t)klo * 2u;
        uint32_t aB0 = Bs + (uint32_t)(wn0 + (lane & 7) + klo) * ROWB + (uint32_t)kofB * 2u;
#pragma unroll
        for (int kk = 0; kk < 2; kk++) {
            uint32_t kb = (uint32_t)kk * 32u;
            uint32_t a[2][4], b[4][2];
#pragma unroll
            for (int mi = 0; mi < 2; mi++)
                ldsm4(a[mi][0], a[mi][1], a[mi][2], a[mi][3],
                      aA0 + (uint32_t)mi * (16u * ROWB) + kb);
#pragma unroll
            for (int p = 0; p < 2; p++)
                ldsm4(b[2 * p][0], b[2 * p][1], b[2 * p + 1][0], b[2 * p + 1][1],
                      aB0 + (uint32_t)p * (16u * ROWB) + kb);
#pragma unroll
            for (int mi = 0; mi < 2; mi++)
#pragma unroll
                for (int ni = 0; ni < 4; ni++)
                    mma_f16(acc[mi][ni][0], acc[mi][ni][1], acc[mi][ni][2], acc[mi][ni][3],
                            a[mi][0], a[mi][1], a[mi][2], a[mi][3],
                            b[ni][0], b[ni][1]);
        }
        __syncthreads();
    }

    // epilogue: scatter fp32 to out[perm]
#pragma unroll
    for (int mi = 0; mi < 2; mi++) {
        int r0 = m0 + wm0 + mi * 16 + grp;
        int r1 = r0 + 8;
        int t0 = (r0 < cnt) ? g_perm[base + r0] : -1;
        int t1 = (r1 < cnt) ? g_perm[base + r1] : -1;
#pragma unroll
        for (int ni = 0; ni < 4; ni++) {
            int c = n0 + wn0 + ni * 8 + 2 * tig;
            if (t0 >= 0) {
                float2 v = make_float2(acc[mi][ni][0], acc[mi][ni][1]);
                *(float2*)&out[(size_t)t0 * D_MODEL + c] = v;
            }
            if (t1 >= 0) {
                float2 v = make_float2(acc[mi][ni][2], acc[mi][ni][3]);
                *(float2*)&out[(size_t)t1 * D_MODEL + c] = v;
            }
        }
    }
}

// ---------------------------------------------------------------
extern "C" void kernel_launch(void* const* d_in, const int* in_sizes, int n_in,
                              void* d_out, int out_size) {
    const float* x  = (const float*)d_in[0];
    const float* ws = (const float*)d_in[1];
    const float* bs = (const float*)d_in[2];
    const float* wi = (const float*)d_in[3];
    const float* wo = (const float*)d_in[4];
    float* out = (float*)d_out;

    static __half* wit_p = nullptr;
    static __half* wot_p = nullptr;
    static __half* xh_p = nullptr;
    static cudaStream_t s1 = nullptr, s2 = nullptr;
    static cudaEvent_t evFork = nullptr, evJoin1 = nullptr, evJoin2 = nullptr;
    if (!wit_p) {
        cudaGetSymbolAddress((void**)&wit_p, g_wit);
        cudaGetSymbolAddress((void**)&wot_p, g_wot);
        cudaGetSymbolAddress((void**)&xh_p, g_xh);
        cudaFuncSetAttribute(gemm1_kernel, cudaFuncAttributeMaxDynamicSharedMemorySize, SMEM1);
        cudaFuncSetAttribute(gemm2_kernel, cudaFuncAttributeMaxDynamicSharedMemorySize, SMEM2);
        cudaStreamCreateWithFlags(&s1, cudaStreamNonBlocking);
        cudaStreamCreateWithFlags(&s2, cudaStreamNonBlocking);
        cudaEventCreateWithFlags(&evFork, cudaEventDisableTiming);
        cudaEventCreateWithFlags(&evJoin1, cudaEventDisableTiming);
        cudaEventCreateWithFlags(&evJoin2, cudaEventDisableTiming);
    }

    // ---- fork from the capture-origin (default) stream ----
    cudaEventRecord(evFork, 0);
    cudaStreamWaitEvent(s1, evFork, 0);
    cudaStreamWaitEvent(s2, evFork, 0);

    // s1: wo transpose-convert (only needed by gemm2)
    cvtT_kernel<<<dim3(D_MODEL / 64, F_FF / 64, N_EXP), 256, 0, s1>>>(wo, wot_p, F_FF, D_MODEL);
    cudaEventRecord(evJoin1, s1);

    // s2: routing chain (only needs x; gemm1 waits on it)
    reset_kernel<<<1, 32, 0, s2>>>();
    router_kernel<<<T_TOK / 8, 256, 0, s2>>>(x, ws, bs);
    finalize_kernel<<<1, 1, 0, s2>>>(out, out_size);
    perm_kernel<<<T_TOK / 256, 256, 0, s2>>>();
    cudaEventRecord(evJoin2, s2);

    // default stream: conversions feeding gemm1
    cvt_kernel<<<512, 256>>>(x, xh_p, T_TOK * D_MODEL / 4);
    cvtT_kernel<<<dim3(F_FF / 64, D_MODEL / 64, N_EXP), 256>>>(wi, wit_p, D_MODEL, F_FF);

    cudaStreamWaitEvent(0, evJoin2, 0);   // routing done
    gemm1_kernel<<<dim3(F_FF / 128, N_EXP * MT1), 256, SMEM1>>>(wit_p);
    cudaStreamWaitEvent(0, evJoin1, 0);   // wot ready
    gemm2_kernel<<<dim3(D_MODEL / 128, N_EXP * MT2), 256, SMEM2>>>(wot_p, out);
}

// round 14
// speedup vs baseline: 1.1120x; 1.0004x over previous
#include <cuda_runtime.h>
#include <cuda_fp16.h>
#include <math.h>
#include <stdint.h>

// Problem constants: B=2, S=2048 -> T=4096 tokens, D=768, F=3072, E=8
#define T_TOK 4096
#define D_MODEL 768
#define F_FF 3072
#define N_EXP 8

#define BK 32
#define STAGES 4
#define NK1 (D_MODEL / BK)   // 24
#define NK2 (F_FF / BK)      // 96
#define MT1 32               // m-tiles/expert, BM=128 (gemm1)
#define MT2 64               // m-tiles/expert, BM=64  (gemm2)

// smem row stride: 40 halves = 80 bytes (conflict-free for LDSM)
#define ROWB 80
#define A1_BYTES (128 * ROWB)
#define B_BYTES  (128 * ROWB)
#define STAGE1 (A1_BYTES + B_BYTES)      // 20480
#define SMEM1 (STAGES * STAGE1)          // 81920
#define A2_BYTES (64 * ROWB)
#define STAGE2 (A2_BYTES + B_BYTES)      // 15360
#define SMEM2 (STAGES * STAGE2)          // 61440

// -------- device scratch --------
__device__ __half g_h[T_TOK * F_FF];          // packed relu(x@wi), fp16
__device__ __half g_xh[T_TOK * D_MODEL];      // fp16 x
__device__ __half g_wit[N_EXP * F_FF * D_MODEL];  // wi transposed: [e][n=F][k=D]
__device__ __half g_wot[N_EXP * D_MODEL * F_FF];  // wo transposed: [e][n=D][k=F]
__device__ int   g_count[N_EXP];
__device__ int   g_base[N_EXP];
__device__ int   g_fill[N_EXP];
__device__ float g_rpsum[N_EXP];
__device__ int   g_routes[T_TOK];
__device__ int   g_perm[T_TOK];
__device__ int   g_arrive;

// ---------------------------------------------------------------
__device__ __forceinline__ uint32_t smem_u32(const void* p) {
    uint32_t a;
    asm("{ .reg .u64 t; cvta.to.shared.u64 t, %1; cvt.u32.u64 %0, t; }"
        : "=r"(a) : "l"(p));
    return a;
}
__device__ __forceinline__ void mma_f16(
    float& c0, float& c1, float& c2, float& c3,
    uint32_t a0, uint32_t a1, uint32_t a2, uint32_t a3,
    uint32_t b0, uint32_t b1)
{
    asm volatile(
        "mma.sync.aligned.m16n8k16.row.col.f32.f16.f16.f32 "
        "{%0,%1,%2,%3}, {%4,%5,%6,%7}, {%8,%9}, {%0,%1,%2,%3};\n"
        : "+f"(c0), "+f"(c1), "+f"(c2), "+f"(c3)
        : "r"(a0), "r"(a1), "r"(a2), "r"(a3), "r"(b0), "r"(b1));
}
__device__ __forceinline__ void ldsm4(uint32_t& r0, uint32_t& r1,
                                      uint32_t& r2, uint32_t& r3, uint32_t addr)
{
    asm volatile("ldmatrix.sync.aligned.m8n8.x4.shared.b16 {%0,%1,%2,%3}, [%4];"
                 : "=r"(r0), "=r"(r1), "=r"(r2), "=r"(r3) : "r"(addr));
}
__device__ __forceinline__ void cp16(uint32_t dst, const void* src, uint32_t sz) {
    asm volatile("cp.async.cg.shared.global [%0], [%1], 16, %2;"
                 :: "r"(dst), "l"(src), "r"(sz) : "memory");
}
__device__ __forceinline__ void cp_commit() {
    asm volatile("cp.async.commit_group;" ::: "memory");
}
template<int N> __device__ __forceinline__ void cp_wait() {
    asm volatile("cp.async.wait_group %0;" :: "n"(N) : "memory");
}

// ---------------------------------------------------------------
__global__ void reset_kernel() {
    int i = threadIdx.x;
    if (i < N_EXP) { g_count[i] = 0; g_fill[i] = 0; g_rpsum[i] = 0.0f; }
    if (i == 0) g_arrive = 0;
}

// fp32 -> fp16 copy (float4 -> 4 halves)
__global__ __launch_bounds__(256) void cvt_kernel(
    const float* __restrict__ src, __half* __restrict__ dst, int n4)
{
    int i = blockIdx.x * blockDim.x + threadIdx.x;
    int stride = gridDim.x * blockDim.x;
    for (; i < n4; i += stride) {
        float4 v = ((const float4*)src)[i];
        __half2 lo = __floats2half2_rn(v.x, v.y);
        __half2 hi = __floats2half2_rn(v.z, v.w);
        uint2 o = make_uint2(*(uint32_t*)&lo, *(uint32_t*)&hi);
        ((uint2*)dst)[i] = o;
    }
}

// fp32 [e][K][N] -> fp16 [e][N][K]  (64x64 tiles, vectorized both sides)
#define TP 66
__global__ __launch_bounds__(256) void cvtT_kernel(
    const float* __restrict__ src, __half* __restrict__ dst, int K, int N)
{
    __shared__ __half tile[64][TP];
    int e = blockIdx.z;
    const float* s = src + (size_t)e * K * N;
    __half* d = dst + (size_t)e * N * K;
    int n0 = blockIdx.x * 64, k0 = blockIdx.y * 64;

    int tx = threadIdx.x & 15, ty = threadIdx.x >> 4;   // 16 x 16
#pragma unroll
    for (int j = 0; j < 4; j++) {
        int k = ty + 16 * j;
        float4 v = *(const float4*)(s + (size_t)(k0 + k) * N + n0 + tx * 4);
        __half2 h01 = __floats2half2_rn(v.x, v.y);
        __half2 h23 = __floats2half2_rn(v.z, v.w);
        *(__half2*)&tile[k][tx * 4]     = h01;
        *(__half2*)&tile[k][tx * 4 + 2] = h23;
    }
    __syncthreads();

    int nr = threadIdx.x >> 2;          // output n-row 0..63
    int kc = (threadIdx.x & 3) * 16;    // k chunk
    __half vals[16];
#pragma unroll
    for (int i = 0; i < 16; i++) vals[i] = tile[kc + i][nr];
    __half* drow = d + (size_t)(n0 + nr) * K + k0 + kc;
    *(uint4*)(drow)     = *(uint4*)&vals[0];
    *(uint4*)(drow + 8) = *(uint4*)&vals[8];
}

// One warp per token; block-level reduction; LAST block folds finalize.
__global__ __launch_bounds__(256) void router_kernel(
    const float* __restrict__ x, const float* __restrict__ w,
    const float* __restrict__ b, float* __restrict__ out, int out_size)
{
    __shared__ float sw[D_MODEL * N_EXP];
    __shared__ float s_rp[N_EXP];
    __shared__ int   s_cnt[N_EXP];
    if (threadIdx.x < N_EXP) { s_rp[threadIdx.x] = 0.0f; s_cnt[threadIdx.x] = 0; }
    for (int i = threadIdx.x; i < D_MODEL * N_EXP; i += blockDim.x) sw[i] = w[i];
    __syncthreads();

    int warp = threadIdx.x >> 5;
    int lane = threadIdx.x & 31;
    int t = blockIdx.x * (blockDim.x >> 5) + warp;

    if (t < T_TOK) {
        float acc[N_EXP];
#pragma unroll
        for (int e = 0; e < N_EXP; e++) acc[e] = 0.0f;
        const float* xr = x + (size_t)t * D_MODEL;
        for (int d = lane; d < D_MODEL; d += 32) {
            float xv = xr[d];
#pragma unroll
            for (int e = 0; e < N_EXP; e++) acc[e] += xv * sw[d * N_EXP + e];
        }
#pragma unroll
        for (int e = 0; e < N_EXP; e++) {
#pragma unroll
            for (int off = 16; off > 0; off >>= 1)
                acc[e] += __shfl_xor_sync(0xFFFFFFFFu, acc[e], off);
        }
        if (lane == 0) {
            float l[N_EXP];
            float mx = -3.4e38f; int am = 0;
#pragma unroll
            for (int e = 0; e < N_EXP; e++) {
                l[e] = acc[e] + b[e];
                if (l[e] > mx) { mx = l[e]; am = e; }
            }
            float s = 0.0f, p[N_EXP];
#pragma unroll
            for (int e = 0; e < N_EXP; e++) { p[e] = __expf(l[e] - mx); s += p[e]; }
            float inv = 1.0f / s;
#pragma unroll
            for (int e = 0; e < N_EXP; e++) atomicAdd(&s_rp[e], p[e] * inv);
            g_routes[t] = am;
            atomicAdd(&s_cnt[am], 1);
        }
    }
    __syncthreads();
    if (threadIdx.x < N_EXP) {
        atomicAdd(&g_rpsum[threadIdx.x], s_rp[threadIdx.x]);
        atomicAdd(&g_count[threadIdx.x], s_cnt[threadIdx.x]);
    }
    __syncthreads();
    if (threadIdx.x == 0) {
        __threadfence();
        int ticket = atomicAdd(&g_arrive, 1);
        if (ticket == (int)gridDim.x - 1) {
            // last block: finalize bases + tail outputs
            int run = 0;
            for (int e = 0; e < N_EXP; e++) { g_base[e] = run; run += g_count[e]; }
            if (out_size >= T_TOK * D_MODEL + 2 * N_EXP + 1) {
                float* tail = out + (size_t)T_TOK * D_MODEL;
                for (int e = 0; e < N_EXP; e++) tail[e] = (float)g_count[e];
                for (int e = 0; e < N_EXP; e++) tail[N_EXP + e] = g_rpsum[e];
                tail[2 * N_EXP] = 0.0f;
            }
        }
    }
}

__global__ void perm_kernel() {
    int t = blockIdx.x * blockDim.x + threadIdx.x;
    if (t >= T_TOK) return;
    int e = g_routes[t];
    int p = g_base[e] + atomicAdd(&g_fill[e], 1);
    g_perm[p] = t;
}

// ---------------------------------------------------------------
// GEMM1: h[m,n] = relu( sum_k xh[perm(m),k] * wit[e][n][k] )  (fp16, fp32 acc)
// BM=128, BN=128, BK=32; covers 4 experts starting at e0.
// ---------------------------------------------------------------
__global__ __launch_bounds__(256, 2) void gemm1_kernel(
    const __half* __restrict__ wi_t, int e0)
{
    int e  = e0 + (blockIdx.y >> 5);
    int mt = blockIdx.y & 31;
    int cnt = g_count[e];
    int m0 = mt * 128;
    if (m0 >= cnt) return;
    int base = g_base[e];
    int n0 = blockIdx.x * 128;
    const __half* Bg = wi_t + (size_t)e * F_FF * D_MODEL;   // [n][k], k-stride D

    extern __shared__ char dsm[];
    uint32_t sbase = smem_u32(dsm);

    int tid  = threadIdx.x;
    int lane = tid & 31, warp = tid >> 5;
    int wm0 = (warp & 1) * 64, wn0 = (warp >> 1) * 32;
    int grp = lane >> 2, tig = lane & 3;

    int mlane = lane & 15;
    int klo   = (lane >> 4) * 8;
    int kofB  = ((lane >> 3) & 1) * 8;

    int arow0 = tid >> 2;
    int achk = tid & 3;
    const __half* apg[2]; uint32_t asz[2];
#pragma unroll
    for (int i = 0; i < 2; i++) {
        int r = m0 + arow0 + i * 64;
        if (r < cnt) { apg[i] = g_xh + (size_t)g_perm[base + r] * D_MODEL; asz[i] = 16; }
        else         { apg[i] = g_xh; asz[i] = 0; }
    }

    float acc[4][4][4];
#pragma unroll
    for (int mi = 0; mi < 4; mi++)
#pragma unroll
        for (int ni = 0; ni < 4; ni++)
#pragma unroll
            for (int q = 0; q < 4; q++) acc[mi][ni][q] = 0.0f;

#pragma unroll
    for (int s = 0; s < STAGES - 1; s++) {
        int kt = s * BK;
        uint32_t Ab = sbase + s * STAGE1;
        uint32_t Bb = Ab + A1_BYTES;
#pragma unroll
        for (int i = 0; i < 2; i++) {
            int row = arow0 + i * 64;
            cp16(Ab + (uint32_t)row * ROWB + (uint32_t)achk * 16u,
                 apg[i] + kt + achk * 8, asz[i]);
            cp16(Bb + (uint32_t)row * ROWB + (uint32_t)achk * 16u,
                 Bg + (size_t)(n0 + row) * D_MODEL + kt + achk * 8, 16);
        }
        cp_commit();
    }

    for (int it = 0; it < NK1; ++it) {
        cp_wait<STAGES - 2>();
        __syncthreads();
        {
            int pt = it + STAGES - 1;
            if (pt < NK1) {
                int s = pt % STAGES;
                int kt = pt * BK;
                uint32_t Ab = sbase + s * STAGE1;
                uint32_t Bb = Ab + A1_BYTES;
#pragma unroll
                for (int i = 0; i < 2; i++) {
                    int row = arow0 + i * 64;
                    cp16(Ab + (uint32_t)row * ROWB + (uint32_t)achk * 16u,
                         apg[i] + kt + achk * 8, asz[i]);
                    cp16(Bb + (uint32_t)row * ROWB + (uint32_t)achk * 16u,
                         Bg + (size_t)(n0 + row) * D_MODEL + kt + achk * 8, 16);
                }
            }
            cp_commit();
        }

        uint32_t As = sbase + (it % STAGES) * STAGE1;
        uint32_t Bs = As + A1_BYTES;
        uint32_t aA0 = As + (uint32_t)(wm0 + mlane) * ROWB + (uint32_t)klo * 2u;
        uint32_t aB0 = Bs + (uint32_t)(wn0 + (lane & 7) + klo) * ROWB + (uint32_t)kofB * 2u;
#pragma unroll
        for (int kk = 0; kk < 2; kk++) {
            uint32_t kb = (uint32_t)kk * 32u;
            uint32_t a[4][4], b[4][2];
#pragma unroll
            for (int mi = 0; mi < 4; mi++)
                ldsm4(a[mi][0], a[mi][1], a[mi][2], a[mi][3],
                      aA0 + (uint32_t)mi * (16u * ROWB) + kb);
#pragma unroll
            for (int p = 0; p < 2; p++)
                ldsm4(b[2 * p][0], b[2 * p][1], b[2 * p + 1][0], b[2 * p + 1][1],
                      aB0 + (uint32_t)p * (16u * ROWB) + kb);
#pragma unroll
            for (int mi = 0; mi < 4; mi++)
#pragma unroll
                for (int ni = 0; ni < 4; ni++)
                    mma_f16(acc[mi][ni][0], acc[mi][ni][1], acc[mi][ni][2], acc[mi][ni][3],
                            a[mi][0], a[mi][1], a[mi][2], a[mi][3],
                            b[ni][0], b[ni][1]);
        }
        // NOTE: no trailing __syncthreads — the top-of-iteration barrier
        // (after cp_wait) already orders stage reuse across warps.
    }

    // epilogue: relu -> fp16 packed g_h
#pragma unroll
    for (int mi = 0; mi < 4; mi++) {
        int r0 = m0 + wm0 + mi * 16 + grp;
        int r1 = r0 + 8;
#pragma unroll
        for (int ni = 0; ni < 4; ni++) {
            int c = n0 + wn0 + ni * 8 + 2 * tig;
            if (r0 < cnt) {
                __half2 v = __floats2half2_rn(fmaxf(acc[mi][ni][0], 0.f),
                                              fmaxf(acc[mi][ni][1], 0.f));
                *(__half2*)&g_h[(size_t)(base + r0) * F_FF + c] = v;
            }
            if (r1 < cnt) {
                __half2 v = __floats2half2_rn(fmaxf(acc[mi][ni][2], 0.f),
                                              fmaxf(acc[mi][ni][3], 0.f));
                *(__half2*)&g_h[(size_t)(base + r1) * F_FF + c] = v;
            }
        }
    }
}

// ---------------------------------------------------------------
// GEMM2: out[perm(m),n] = sum_k h[m,k] * wot[e][n][k]
// BM=64, BN=128, BK=32; covers 4 experts starting at e0.
// ---------------------------------------------------------------
__global__ __launch_bounds__(256, 2) void gemm2_kernel(
    const __half* __restrict__ wo_t, float* __restrict__ out, int e0)
{
    int e  = e0 + (blockIdx.y >> 6);
    int mt = blockIdx.y & 63;
    int cnt = g_count[e];
    int m0 = mt * 64;
    if (m0 >= cnt) return;
    int base = g_base[e];
    int n0 = blockIdx.x * 128;
    const __half* Bg = wo_t + (size_t)e * D_MODEL * F_FF;   // [n][k], k-stride F

    extern __shared__ char dsm[];
    uint32_t sbase = smem_u32(dsm);

    int tid  = threadIdx.x;
    int lane = tid & 31, warp = tid >> 5;
    int wm0 = (warp & 1) * 32, wn0 = (warp >> 1) * 32;
    int grp = lane >> 2, tig = lane & 3;

    int mlane = lane & 15;
    int klo   = (lane >> 4) * 8;
    int kofB  = ((lane >> 3) & 1) * 8;

    int arow = tid >> 2;
    int achk = tid & 3;
    uint32_t asz = (m0 + arow < cnt) ? 16u : 0u;
    const __half* apg = g_h + (size_t)(base + ((m0 + arow < cnt) ? (m0 + arow) : 0)) * F_FF;

    float acc[2][4][4];
#pragma unroll
    for (int mi = 0; mi < 2; mi++)
#pragma unroll
        for (int ni = 0; ni < 4; ni++)
#pragma unroll
            for (int q = 0; q < 4; q++) acc[mi][ni][q] = 0.0f;

#pragma unroll
    for (int s = 0; s < STAGES - 1; s++) {
        int kt = s * BK;
        uint32_t Ab = sbase + s * STAGE2;
        uint32_t Bb = Ab + A2_BYTES;
        cp16(Ab + (uint32_t)arow * ROWB + (uint32_t)achk * 16u, apg + kt + achk * 8, asz);
#pragma unroll
        for (int i = 0; i < 2; i++) {
            int row = arow + i * 64;
            cp16(Bb + (uint32_t)row * ROWB + (uint32_t)achk * 16u,
                 Bg + (size_t)(n0 + row) * F_FF + kt + achk * 8, 16);
        }
        cp_commit();
    }

    for (int it = 0; it < NK2; ++it) {
        cp_wait<STAGES - 2>();
        __syncthreads();
        {
            int pt = it + STAGES - 1;
            if (pt < NK2) {
                int s = pt % STAGES;
                int kt = pt * BK;
                uint32_t Ab = sbase + s * STAGE2;
                uint32_t Bb = Ab + A2_BYTES;
                cp16(Ab + (uint32_t)arow * ROWB + (uint32_t)achk * 16u, apg + kt + achk * 8, asz);
#pragma unroll
                for (int i = 0; i < 2; i++) {
                    int row = arow + i * 64;
                    cp16(Bb + (uint32_t)row * ROWB + (uint32_t)achk * 16u,
                         Bg + (size_t)(n0 + row) * F_FF + kt + achk * 8, 16);
                }
            }
            cp_commit();
        }

        uint32_t As = sbase + (it % STAGES) * STAGE2;
        uint32_t Bs = As + A2_BYTES;
        uint32_t aA0 = As + (uint32_t)(wm0 + mlane) * ROWB + (uint32_t)klo * 2u;
        uint32_t aB0 = Bs + (uint32_t)(wn0 + (lane & 7) + klo) * ROWB + (uint32_t)kofB * 2u;
#pragma unroll
        for (int kk = 0; kk < 2; kk++) {
            uint32_t kb = (uint32_t)kk * 32u;
            uint32_t a[2][4], b[4][2];
#pragma unroll
            for (int mi = 0; mi < 2; mi++)
                ldsm4(a[mi][0], a[mi][1], a[mi][2], a[mi][3],
                      aA0 + (uint32_t)mi * (16u * ROWB) + kb);
#pragma unroll
            for (int p = 0; p < 2; p++)
                ldsm4(b[2 * p][0], b[2 * p][1], b[2 * p + 1][0], b[2 * p + 1][1],
                      aB0 + (uint32_t)p * (16u * ROWB) + kb);
#pragma unroll
            for (int mi = 0; mi < 2; mi++)
#pragma unroll
                for (int ni = 0; ni < 4; ni++)
                    mma_f16(acc[mi][ni][0], acc[mi][ni][1], acc[mi][ni][2], acc[mi][ni][3],
                            a[mi][0], a[mi][1], a[mi][2], a[mi][3],
                            b[ni][0], b[ni][1]);
        }
        // no trailing barrier (see gemm1)
    }

    // epilogue: scatter fp32 to out[perm]
#pragma unroll
    for (int mi = 0; mi < 2; mi++) {
        int r0 = m0 + wm0 + mi * 16 + grp;
        int r1 = r0 + 8;
        int t0 = (r0 < cnt) ? g_perm[base + r0] : -1;
        int t1 = (r1 < cnt) ? g_perm[base + r1] : -1;
#pragma unroll
        for (int ni = 0; ni < 4; ni++) {
            int c = n0 + wn0 + ni * 8 + 2 * tig;
            if (t0 >= 0) {
                float2 v = make_float2(acc[mi][ni][0], acc[mi][ni][1]);
                *(float2*)&out[(size_t)t0 * D_MODEL + c] = v;
            }
            if (t1 >= 0) {
                float2 v = make_float2(acc[mi][ni][2], acc[mi][ni][3]);
                *(float2*)&out[(size_t)t1 * D_MODEL + c] = v;
            }
        }
    }
}

// ---------------------------------------------------------------
extern "C" void kernel_launch(void* const* d_in, const int* in_sizes, int n_in,
                              void* d_out, int out_size) {
    const float* x  = (const float*)d_in[0];
    const float* ws = (const float*)d_in[1];
    const float* bs = (const float*)d_in[2];
    const float* wi = (const float*)d_in[3];
    const float* wo = (const float*)d_in[4];
    float* out = (float*)d_out;

    static __half* wit_p = nullptr;
    static __half* wot_p = nullptr;
    static __half* xh_p = nullptr;
    static cudaStream_t s1 = nullptr, s2 = nullptr;
    static cudaEvent_t evFork = nullptr, evWo = nullptr, evRoute = nullptr,
                       evG1A = nullptr, evG2A = nullptr;
    if (!wit_p) {
        cudaGetSymbolAddress((void**)&wit_p, g_wit);
        cudaGetSymbolAddress((void**)&wot_p, g_wot);
        cudaGetSymbolAddress((void**)&xh_p, g_xh);
        cudaFuncSetAttribute(gemm1_kernel, cudaFuncAttributeMaxDynamicSharedMemorySize, SMEM1);
        cudaFuncSetAttribute(gemm2_kernel, cudaFuncAttributeMaxDynamicSharedMemorySize, SMEM2);
        cudaStreamCreateWithFlags(&s1, cudaStreamNonBlocking);
        cudaStreamCreateWithFlags(&s2, cudaStreamNonBlocking);
        cudaEventCreateWithFlags(&evFork, cudaEventDisableTiming);
        cudaEventCreateWithFlags(&evWo, cudaEventDisableTiming);
        cudaEventCreateWithFlags(&evRoute, cudaEventDisableTiming);
        cudaEventCreateWithFlags(&evG1A, cudaEventDisableTiming);
        cudaEventCreateWithFlags(&evG2A, cudaEventDisableTiming);
    }

    // ---- fork from capture-origin (default) stream ----
    cudaEventRecord(evFork, 0);
    cudaStreamWaitEvent(s1, evFork, 0);
    cudaStreamWaitEvent(s2, evFork, 0);

    // s1: wo transpose-convert (needed by gemm2 only)
    cvtT_kernel<<<dim3(D_MODEL / 64, F_FF / 64, N_EXP), 256, 0, s1>>>(wo, wot_p, F_FF, D_MODEL);
    cudaEventRecord(evWo, s1);

    // s2: routing chain (finalize folded into router's last block)
    reset_kernel<<<1, 32, 0, s2>>>();
    router_kernel<<<T_TOK / 8, 256, 0, s2>>>(x, ws, bs, out, out_size);
    perm_kernel<<<T_TOK / 256, 256, 0, s2>>>();
    cudaEventRecord(evRoute, s2);

    // default stream: conversions feeding gemm1
    cvt_kernel<<<512, 256>>>(x, xh_p, T_TOK * D_MODEL / 4);
    cvtT_kernel<<<dim3(F_FF / 64, D_MODEL / 64, N_EXP), 256>>>(wi, wit_p, D_MODEL, F_FF);

    cudaStreamWaitEvent(0, evRoute, 0);          // routing done
    // gemm1 first half (experts 0-3), then signal; second half continues
    gemm1_kernel<<<dim3(F_FF / 128, 4 * MT1), 256, SMEM1>>>(wit_p, 0);
    cudaEventRecord(evG1A, 0);
    gemm1_kernel<<<dim3(F_FF / 128, 4 * MT1), 256, SMEM1>>>(wit_p, 4);

    // s1: gemm2 first half overlaps gemm1 second half
    cudaStreamWaitEvent(s1, evG1A, 0);           // (wo already done on s1)
    gemm2_kernel<<<dim3(D_MODEL / 128, 4 * MT2), 256, SMEM2, s1>>>(wot_p, out, 0);
    cudaEventRecord(evG2A, s1);

    // default: gemm2 second half (after gemm1 second half in program order)
    cudaStreamWaitEvent(0, evWo, 0);             // wot ready
    gemm2_kernel<<<dim3(D_MODEL / 128, 4 * MT2), 256, SMEM2>>>(wot_p, out, 4);
    cudaStreamWaitEvent(0, evG2A, 0);            // join s1
}